// round 3
// baseline (speedup 1.0000x reference)
#include <cuda_runtime.h>
#include <cstdint>

// Shapes
#define BATCH 1024
#define CIN   512
#define KDIM  768           // (j,l) contraction: j*256 + l
#define NDIM  1536          // k*512 + i
#define MDIM  (BATCH * 49)  // 50176 = b*49 + n*7 + w

// Scratch (static __device__ — no allocations allowed)
__device__ float g_S[(size_t)MDIM * KDIM];   // 154 MB
__device__ float g_W3[KDIM * NDIM];          // 4.7 MB
__device__ float g_G[(size_t)MDIM * NDIM];   // 308 MB

// ---------------------------------------------------------------------------
// W3[(j*256+l)*1536 + k*512 + i] = W[l,j,k,i]   (W is (256,3,3,512) row-major)
// ---------------------------------------------------------------------------
__global__ void build_w3_k(const float* __restrict__ W) {
    int idx = blockIdx.x * 256 + threadIdx.x;
    if (idx >= KDIM * NDIM) return;
    int col = idx % NDIM;
    int c2  = idx / NDIM;
    int k = col >> 9;          // col / 512
    int i = col & 511;
    int j = c2 >> 8;
    int l = c2 & 255;
    g_W3[idx] = W[(((l * 3 + j) * 3 + k) << 9) + i];
}

// ---------------------------------------------------------------------------
// S[b][n][w][j*256+l] = xz(b,256+l,(n+6)%7 + j-1, w) + xz(b,l, n+j-1, w)
// One CTA per b; x[b] staged in SMEM (100 KB), both global streams coalesced.
// ---------------------------------------------------------------------------
__global__ void build_s_k(const float* __restrict__ x) {
    extern __shared__ float sx[];  // 512*49 floats
    int b = blockIdx.x;
    const float4* xb = (const float4*)(x + (size_t)b * (CIN * 49));
    for (int i = threadIdx.x; i < CIN * 49 / 4; i += blockDim.x)
        ((float4*)sx)[i] = xb[i];
    __syncthreads();

    float* Sb = g_S + (size_t)b * (49 * KDIM);
    for (int e = threadIdx.x; e < 49 * KDIM; e += blockDim.x) {
        int c2 = e % KDIM;
        int nw = e / KDIM;
        int n = nw / 7, w = nw - n * 7;
        int j = c2 >> 8, l = c2 & 255;
        int r0 = n + j - 1;
        int n2 = n + 6; if (n2 >= 7) n2 -= 7;
        int r1 = n2 + j - 1;
        float v = 0.f;
        if ((unsigned)r0 < 7u) v += sx[l * 49 + r0 * 7 + w];
        if ((unsigned)r1 < 7u) v += sx[(256 + l) * 49 + r1 * 7 + w];
        Sb[e] = v;
    }
}

// ---------------------------------------------------------------------------
// SGEMM: G[M=50176][N=1536] = S[M][768] * W3[768][1536]
// BM=BN=128, BK=16, 256 threads, 8x8 per-thread microtile.
// M,N,K all divide tile sizes exactly -> no bounds checks.
// ---------------------------------------------------------------------------
__global__ __launch_bounds__(256) void gemm_k() {
    __shared__ float As[16][128];
    __shared__ float Bs[16][128];
    const int tid = threadIdx.x;
    const int ty = tid >> 4;   // 0..15
    const int tx = tid & 15;   // 0..15

    const float* Ab = g_S + (size_t)blockIdx.y * 128 * KDIM;
    const float* Bb = g_W3 + blockIdx.x * 128;

    float acc[8][8];
#pragma unroll
    for (int m = 0; m < 8; m++)
#pragma unroll
        for (int n = 0; n < 8; n++) acc[m][n] = 0.f;

    for (int k0 = 0; k0 < KDIM; k0 += 16) {
        // A tile 128x16 -> As[k][m] (transposed), 512 float4, 2 per thread
#pragma unroll
        for (int f = tid; f < 512; f += 256) {
            int r  = f >> 2;
            int c4 = (f & 3) << 2;
            float4 v = *(const float4*)(Ab + (size_t)r * KDIM + k0 + c4);
            As[c4 + 0][r] = v.x;
            As[c4 + 1][r] = v.y;
            As[c4 + 2][r] = v.z;
            As[c4 + 3][r] = v.w;
        }
        // B tile 16x128 -> Bs[k][n], 512 float4, 2 per thread
#pragma unroll
        for (int f = tid; f < 512; f += 256) {
            int r  = f >> 5;
            int c4 = (f & 31) << 2;
            *(float4*)&Bs[r][c4] = *(const float4*)(Bb + (size_t)(k0 + r) * NDIM + c4);
        }
        __syncthreads();

#pragma unroll
        for (int kk = 0; kk < 16; kk++) {
            float a[8], bb[8];
            *(float4*)(a)      = *(const float4*)&As[kk][ty * 8];
            *(float4*)(a + 4)  = *(const float4*)&As[kk][ty * 8 + 4];
            *(float4*)(bb)     = *(const float4*)&Bs[kk][tx * 8];
            *(float4*)(bb + 4) = *(const float4*)&Bs[kk][tx * 8 + 4];
#pragma unroll
            for (int m = 0; m < 8; m++)
#pragma unroll
                for (int n = 0; n < 8; n++)
                    acc[m][n] += a[m] * bb[n];
        }
        __syncthreads();
    }

    float* Cb = g_G + ((size_t)blockIdx.y * 128 + ty * 8) * NDIM + blockIdx.x * 128 + tx * 8;
#pragma unroll
    for (int m = 0; m < 8; m++) {
        *(float4*)(Cb + (size_t)m * NDIM) =
            make_float4(acc[m][0], acc[m][1], acc[m][2], acc[m][3]);
        *(float4*)(Cb + (size_t)m * NDIM + 4) =
            make_float4(acc[m][4], acc[m][5], acc[m][6], acc[m][7]);
    }
}

// ---------------------------------------------------------------------------
// out[b,i,n,p] = sum_k [0 <= p+k-1 < 7] * G[b, n, (p+k+5)%7][k*512+i]
// CTA per (b,n): 7x1536 G rows are contiguous -> coalesced SMEM stage.
// ---------------------------------------------------------------------------
__global__ void epilogue_k(float* __restrict__ out) {
    __shared__ float sg[7 * NDIM];  // 43 KB
    int b = blockIdx.x / 7;
    int n = blockIdx.x % 7;
    const float4* Gb = (const float4*)(g_G + (size_t)(b * 49 + n * 7) * NDIM);
    for (int i = threadIdx.x; i < 7 * NDIM / 4; i += blockDim.x)
        ((float4*)sg)[i] = Gb[i];
    __syncthreads();

    for (int e = threadIdx.x; e < 512 * 7; e += blockDim.x) {
        int i = e / 7;
        int p = e - i * 7;
        float v = 0.f;
#pragma unroll
        for (int k = 0; k < 3; k++) {
            int q = p + k - 1;
            if ((unsigned)q < 7u) {
                int w = p + k + 5; if (w >= 7) w -= 7;   // (p+k-2) mod 7
                v += sg[w * NDIM + (k << 9) + i];
            }
        }
        out[(((size_t)b * 512 + i) * 7 + n) * 7 + p] = v;
    }
}

// ---------------------------------------------------------------------------
extern "C" void kernel_launch(void* const* d_in, const int* in_sizes, int n_in,
                              void* d_out, int out_size) {
    const float* x = (const float*)d_in[0];   // (1024,512,7,7)
    const float* W = (const float*)d_in[1];   // (256,3,3,512)
    float* out = (float*)d_out;               // (1024,512,7,7)

    cudaFuncSetAttribute(build_s_k, cudaFuncAttributeMaxDynamicSharedMemorySize,
                         CIN * 49 * 4);

    build_w3_k<<<(KDIM * NDIM + 255) / 256, 256>>>(W);
    build_s_k<<<BATCH, 256, CIN * 49 * 4>>>(x);

    dim3 grid(NDIM / 128, MDIM / 128);  // (12, 392)
    gemm_k<<<grid, 256>>>();

    epilogue_k<<<BATCH * 7, 256>>>(out);
}

// round 7
// speedup vs baseline: 3.3676x; 3.3676x over previous
#include <cuda_runtime.h>
#include <cuda_bf16.h>
#include <cstdint>

// Shapes
#define BATCH 1024
#define CIN   512
#define KDIM  768            // contraction: c2 = j*256 + l
#define NDIM  1536           // n = k*512 + i
#define MDIM  (BATCH * 49)   // 50176 = b*49 + n*7 + w

// Scratch (static __device__ — no allocations allowed)
__device__ __align__(1024) __nv_bfloat16 g_Shi[(size_t)MDIM * KDIM];  // 77 MB
__device__ __align__(1024) __nv_bfloat16 g_Slo[(size_t)MDIM * KDIM];  // 77 MB
__device__ __align__(1024) __nv_bfloat16 g_Whi[(size_t)KDIM * NDIM];  // [K][N], 2.4 MB
__device__ __align__(1024) __nv_bfloat16 g_Wlo[(size_t)KDIM * NDIM];
__device__ __align__(1024) float g_G[(size_t)MDIM * NDIM];            // 308 MB

// ---------------------------------------------------------------------------
// PTX helpers — compute_103-safe only (cp.async, ldmatrix, mma.sync)
// ---------------------------------------------------------------------------
__device__ __forceinline__ uint32_t smem_u32(const void* p) {
    uint32_t a;
    asm("{ .reg .u64 t; cvta.to.shared.u64 t, %1; cvt.u32.u64 %0, t; }" : "=r"(a) : "l"(p));
    return a;
}
#define CP16(dst, src) \
    asm volatile("cp.async.cg.shared.global [%0], [%1], 16;" :: "r"(dst), "l"(src))
#define CP_COMMIT() asm volatile("cp.async.commit_group;" ::: "memory")
#define CP_WAIT2()  asm volatile("cp.async.wait_group 2;" ::: "memory")

#define LDSM_X4(R, addr)                                                      \
    asm volatile("ldmatrix.sync.aligned.m8n8.x4.shared.b16 {%0,%1,%2,%3}, [%4];" \
        : "=r"((R)[0]), "=r"((R)[1]), "=r"((R)[2]), "=r"((R)[3]) : "r"(addr))
#define LDSM_X4_T(R, addr)                                                    \
    asm volatile("ldmatrix.sync.aligned.m8n8.x4.trans.shared.b16 {%0,%1,%2,%3}, [%4];" \
        : "=r"((R)[0]), "=r"((R)[1]), "=r"((R)[2]), "=r"((R)[3]) : "r"(addr))

#define MMA16816(D, A, B0, B1)                                                \
    asm volatile("mma.sync.aligned.m16n8k16.row.col.f32.bf16.bf16.f32 "       \
        "{%0,%1,%2,%3}, {%4,%5,%6,%7}, {%8,%9}, {%0,%1,%2,%3};"               \
        : "+f"((D)[0]), "+f"((D)[1]), "+f"((D)[2]), "+f"((D)[3])              \
        : "r"((A)[0]), "r"((A)[1]), "r"((A)[2]), "r"((A)[3]),                 \
          "r"(B0), "r"(B1))

// ---------------------------------------------------------------------------
// W hi/lo, layout [K=768][N=1536]: g_W[c2*1536 + n] = split(W[l,j,k,i])
//   n = k*512 + i, c2 = j*256 + l
// ---------------------------------------------------------------------------
__global__ void build_w_k(const float* __restrict__ W) {
    int idx = blockIdx.x * 256 + threadIdx.x;
    if (idx >= KDIM * NDIM) return;
    int n  = idx % NDIM;
    int c2 = idx / NDIM;
    int k = n >> 9, i = n & 511;
    int j = c2 >> 8, l = c2 & 255;
    float v = W[(((l * 3 + j) * 3 + k) << 9) + i];
    __nv_bfloat16 hi = __float2bfloat16(v);
    __nv_bfloat16 lo = __float2bfloat16(v - __bfloat162float(hi));
    g_Whi[idx] = hi;
    g_Wlo[idx] = lo;
}

// ---------------------------------------------------------------------------
// S hi/lo: S[b][n][w][j*256+l] = xz(b,256+l,(n+6)%7+j-1,w) + xz(b,l,n+j-1,w)
// ---------------------------------------------------------------------------
__global__ void build_s_k(const float* __restrict__ x) {
    extern __shared__ float sx[];  // 512*49 floats
    int b = blockIdx.x;
    const float4* xb = (const float4*)(x + (size_t)b * (CIN * 49));
    for (int i = threadIdx.x; i < CIN * 49 / 4; i += blockDim.x)
        ((float4*)sx)[i] = xb[i];
    __syncthreads();

    size_t base = (size_t)b * (49 * KDIM);
    for (int e = threadIdx.x; e < 49 * KDIM; e += blockDim.x) {
        int c2 = e % KDIM;
        int nw = e / KDIM;
        int n = nw / 7, w = nw - n * 7;
        int j = c2 >> 8, l = c2 & 255;
        int r0 = n + j - 1;
        int n2 = n + 6; if (n2 >= 7) n2 -= 7;
        int r1 = n2 + j - 1;
        float v = 0.f;
        if ((unsigned)r0 < 7u) v += sx[l * 49 + r0 * 7 + w];
        if ((unsigned)r1 < 7u) v += sx[(256 + l) * 49 + r1 * 7 + w];
        __nv_bfloat16 hi = __float2bfloat16(v);
        __nv_bfloat16 lo = __float2bfloat16(v - __bfloat162float(hi));
        g_Shi[base + e] = hi;
        g_Slo[base + e] = lo;
    }
}

// ---------------------------------------------------------------------------
// bf16 GEMM via mma.sync.m16n8k16 (compute_103-safe tensor path).
// G[50176][1536] = Shi*Whi + Shi*Wlo + Slo*Whi  (fp32 accum; lo*lo dropped)
// CTA 128x128, BK=32, 72 virtual k-chunks (3 segments x 24), 3-stage cp.async.
// 8 warps in 4(M) x 2(N) grid; warp tile 32x64.
// SMEM per stage: A[128][40] bf16 (10240B) + B[32][136] bf16 (8704B) = 18944B.
// ---------------------------------------------------------------------------
#define LDA_S 40
#define LDB_S 136
#define STG_B 18944
#define NCHUNK 72

__global__ __launch_bounds__(256) void gemm_k() {
    extern __shared__ __align__(128) char smem[];
    const uint32_t sb = smem_u32(smem);
    const int tid  = threadIdx.x;
    const int wid  = tid >> 5;
    const int lane = tid & 31;
    const int warp_m = wid & 3;      // 0..3 -> m offset *32
    const int warp_n = wid >> 2;     // 0..1 -> n offset *64

    const size_t m0 = (size_t)blockIdx.y * 128;
    const int    n0 = blockIdx.x * 128;

    const char* Ahi = (const char*)g_Shi + m0 * (KDIM * 2);
    const char* Alo = (const char*)g_Slo + m0 * (KDIM * 2);
    const char* Bhi = (const char*)g_Whi + (size_t)n0 * 2;
    const char* Blo = (const char*)g_Wlo + (size_t)n0 * 2;

    float acc[2][8][4];
#pragma unroll
    for (int mt = 0; mt < 2; mt++)
#pragma unroll
        for (int nt = 0; nt < 8; nt++)
#pragma unroll
            for (int q = 0; q < 4; q++) acc[mt][nt][q] = 0.f;

    auto issue = [&](int kc) {
        int seg = kc / 24, kk = kc - seg * 24;
        const char* As = (seg < 2) ? Ahi : Alo;
        const char* Bs = (seg == 1) ? Blo : Bhi;
        const uint32_t st = sb + (kc % 3) * STG_B;
        const int k0 = kk * 32;
        // A: 128 rows x 32 bf16; 4 x16B per row; 512 chunks / 256 thr
#pragma unroll
        for (int h = 0; h < 2; h++) {
            int c = h * 256 + tid;
            int r = c >> 2, cc = (c & 3) * 8;
            CP16(st + (r * LDA_S + cc) * 2,
                 As + (size_t)r * (KDIM * 2) + (k0 + cc) * 2);
        }
        // B: 32 rows x 128 bf16; 16 x16B per row; 512 chunks / 256 thr
#pragma unroll
        for (int h = 0; h < 2; h++) {
            int c = h * 256 + tid;
            int r = c >> 4, cc = (c & 15) * 8;
            CP16(st + 10240 + (r * LDB_S + cc) * 2,
                 Bs + (size_t)(k0 + r) * (NDIM * 2) + cc * 2);
        }
    };

    issue(0); CP_COMMIT();
    issue(1); CP_COMMIT();

    for (int kc = 0; kc < NCHUNK; kc++) {
        if (kc + 2 < NCHUNK) issue(kc + 2);
        CP_COMMIT();                 // unconditional: keeps group accounting uniform
        CP_WAIT2();                  // all but last 2 groups done -> stage kc ready
        __syncthreads();

        const uint32_t As = sb + (kc % 3) * STG_B;
        const uint32_t Bs = As + 10240;
        // ldmatrix lane addressing: row = lane&15, col-block = (lane>>4)*8
        const int lr = lane & 15, lc = (lane >> 4) * 8;

#pragma unroll
        for (int ks = 0; ks < 2; ks++) {
            uint32_t af[2][4];
#pragma unroll
            for (int mt = 0; mt < 2; mt++)
                LDSM_X4(af[mt], As + ((warp_m * 32 + mt * 16 + lr) * LDA_S
                                      + ks * 16 + lc) * 2);
            uint32_t bf[4][4];
#pragma unroll
            for (int nt2 = 0; nt2 < 4; nt2++)
                LDSM_X4_T(bf[nt2], Bs + ((ks * 16 + lr) * LDB_S
                                         + warp_n * 64 + nt2 * 16 + lc) * 2);
#pragma unroll
            for (int mt = 0; mt < 2; mt++)
#pragma unroll
                for (int nt = 0; nt < 8; nt++)
                    MMA16816(acc[mt][nt], af[mt],
                             bf[nt >> 1][(nt & 1) * 2],
                             bf[nt >> 1][(nt & 1) * 2 + 1]);
        }
        __syncthreads();             // stage reuse guard
    }

    // Write C: d0,d1 -> row g cols 2*tig; d2,d3 -> row g+8
    const int g = lane >> 2, tig = lane & 3;
#pragma unroll
    for (int mt = 0; mt < 2; mt++) {
        size_t mrow = m0 + warp_m * 32 + mt * 16 + g;
        float* c0 = g_G + mrow * NDIM + n0 + warp_n * 64 + tig * 2;
        float* c1 = c0 + 8 * NDIM;
#pragma unroll
        for (int nt = 0; nt < 8; nt++) {
            *(float2*)(c0 + nt * 8) = make_float2(acc[mt][nt][0], acc[mt][nt][1]);
            *(float2*)(c1 + nt * 8) = make_float2(acc[mt][nt][2], acc[mt][nt][3]);
        }
    }
}

// ---------------------------------------------------------------------------
// out[b,i,n,p] = sum_k [0 <= p+k-1 < 7] * G[b, n, (p+k+5)%7][k*512+i]
// ---------------------------------------------------------------------------
__global__ void epilogue_k(float* __restrict__ out) {
    __shared__ float sg[7 * NDIM];  // 43 KB
    int b = blockIdx.x / 7;
    int n = blockIdx.x % 7;
    const float4* Gb = (const float4*)(g_G + (size_t)(b * 49 + n * 7) * NDIM);
    for (int i = threadIdx.x; i < 7 * NDIM / 4; i += blockDim.x)
        ((float4*)sg)[i] = Gb[i];
    __syncthreads();

    for (int e = threadIdx.x; e < 512 * 7; e += blockDim.x) {
        int i = e / 7;
        int p = e - i * 7;
        float v = 0.f;
#pragma unroll
        for (int k = 0; k < 3; k++) {
            int q = p + k - 1;
            if ((unsigned)q < 7u) {
                int w = p + k + 5; if (w >= 7) w -= 7;
                v += sg[w * NDIM + (k << 9) + i];
            }
        }
        out[(((size_t)b * 512 + i) * 7 + n) * 7 + p] = v;
    }
}

// ---------------------------------------------------------------------------
extern "C" void kernel_launch(void* const* d_in, const int* in_sizes, int n_in,
                              void* d_out, int out_size) {
    const float* x = (const float*)d_in[0];   // (1024,512,7,7)
    const float* W = (const float*)d_in[1];   // (256,3,3,512)
    float* out = (float*)d_out;               // (1024,512,7,7)

    cudaFuncSetAttribute(build_s_k, cudaFuncAttributeMaxDynamicSharedMemorySize,
                         CIN * 49 * 4);
    cudaFuncSetAttribute(gemm_k, cudaFuncAttributeMaxDynamicSharedMemorySize,
                         3 * STG_B);

    build_w_k<<<(KDIM * NDIM + 255) / 256, 256>>>(W);
    build_s_k<<<BATCH, 256, CIN * 49 * 4>>>(x);

    dim3 grid(NDIM / 128, MDIM / 128);  // (12, 392)
    gemm_k<<<grid, 256, 3 * STG_B>>>();

    epilogue_k<<<BATCH * 7, 256>>>(out);
}